// round 13
// baseline (speedup 1.0000x reference)
#include <cuda_runtime.h>
#include <cuda_fp16.h>
#include <cstdint>

#define NN 4096
#define INF 256
#define OF 64
#define NH 4

// ---------------------------------------------------------------------------
// Scratch globals
// ---------------------------------------------------------------------------
__device__ float4   g_idat[NH][NN];        // {src, exp(src), exp(0.2*src), 0}
__device__ unsigned g_adjT[NN / 32][NN];   // adjacency bits [wordcol][row]
// xt tiles: per (h,chunk): fp16 seg [64 k][64 n] (rows 144B) + 1KB tail:
//   [9216,9472) dst f32[64]   [9472,9728) e1 f32[64]   [9728,9984) e2 f32[64]
#define SEGB 9216
#define VCH  10240
__device__ __align__(16) char g_Vt[NH * 64 * VCH];

// ---------------------------------------------------------------------------
// PTX helpers (family-generic: no tcgen05 on compute_103 virtual target)
// ---------------------------------------------------------------------------
__device__ __forceinline__ uint32_t smem_u32(const void* p) {
    uint32_t a;
    asm("{ .reg .u64 t; cvta.to.shared.u64 t, %1; cvt.u32.u64 %0, t; }" : "=r"(a) : "l"(p));
    return a;
}
#define MBAR_INIT(a, n) asm volatile("mbarrier.init.shared.b64 [%0], %1;" :: "r"(a), "r"(n) : "memory")
#define MBAR_WAIT(a, ph) do {                                                            \
    uint32_t _m = (a), _p = (ph), _d;                                                    \
    asm volatile("{ .reg .pred p; mbarrier.try_wait.parity.acquire.cta.shared::cta.b64 " \
                 "p, [%1], %2; selp.b32 %0, 1, 0, p; }" : "=r"(_d) : "r"(_m), "r"(_p) : "memory"); \
    if (!_d) {                                                                           \
        asm volatile("{ .reg .pred P1; WL_%=: mbarrier.try_wait.parity.acquire.cta.shared::cta.b64 " \
                     "P1, [%0], %1, 0x989680; @P1 bra.uni WD_%=; bra.uni WL_%=; WD_%=: }" \
                     :: "r"(_m), "r"(_p) : "memory");                                    \
    }                                                                                    \
} while (0)
#define MBAR_ARRIVE(a) asm volatile("mbarrier.arrive.shared.b64 _, [%0];" :: "r"(a) : "memory")

#define LDSM_X4(r, a)                                                         \
    asm volatile("ldmatrix.sync.aligned.m8n8.x4.shared.b16 {%0,%1,%2,%3}, [%4];" \
        : "=r"((r)[0]), "=r"((r)[1]), "=r"((r)[2]), "=r"((r)[3]) : "r"(a))
#define LDSM_X4T(r, a)                                                        \
    asm volatile("ldmatrix.sync.aligned.m8n8.x4.trans.shared.b16 {%0,%1,%2,%3}, [%4];" \
        : "=r"((r)[0]), "=r"((r)[1]), "=r"((r)[2]), "=r"((r)[3]) : "r"(a))

#define MMA(d, a, b0_, b1_)                                                   \
    asm volatile("mma.sync.aligned.m16n8k16.row.col.f32.f16.f16.f32 "         \
        "{%0,%1,%2,%3},{%4,%5,%6,%7},{%8,%9},{%0,%1,%2,%3};"                  \
        : "+f"((d)[0]), "+f"((d)[1]), "+f"((d)[2]), "+f"((d)[3])              \
        : "r"((a)[0]), "r"((a)[1]), "r"((a)[2]), "r"((a)[3]), "r"(b0_), "r"(b1_))

// ---------------------------------------------------------------------------
// Kernel 1: adjacency bitpack (transposed), 16 elements/thread (measured best)
// ---------------------------------------------------------------------------
__global__ __launch_bounds__(256) void k_bitpack(const int* __restrict__ adj) {
    size_t tid = (size_t)blockIdx.x * 256 + threadIdx.x;
    int lane = threadIdx.x & 31;
    size_t base = tid * 16;
    int row = (int)(base >> 12), col = (int)(base & 4095);
    unsigned bits = 0;
    #pragma unroll
    for (int e = 0; e < 4; e++) {
        int4 v = *(const int4*)(adj + (size_t)row * NN + col + e * 4);
        bits |= ((unsigned)(v.x > 0) << (e * 4)) | ((unsigned)(v.y > 0) << (e * 4 + 1)) |
                ((unsigned)(v.z > 0) << (e * 4 + 2)) | ((unsigned)(v.w > 0) << (e * 4 + 3));
    }
    unsigned val = bits << (((unsigned)(col >> 4) & 1u) * 16u);
    val |= __shfl_xor_sync(0xffffffffu, val, 1);
    if ((lane & 1) == 0) g_adjT[col >> 5][row] = val;
}

// ---------------------------------------------------------------------------
// Kernel 2: xt GEMM + per-row scalars + fp16 xt-tile build (j-data in tail).
// ---------------------------------------------------------------------------
__global__ __launch_bounds__(256) void k_xtv(const float* __restrict__ x,
                                             const float* __restrict__ W,
                                             const float* __restrict__ a) {
    __shared__ float sx[16][68];
    __shared__ float sw[16][64];
    __shared__ float sxt[64][68];
    const int h = blockIdx.y, n0 = blockIdx.x * 64, t = threadIdx.x;
    const int tx = t & 15, ty = t >> 4;
    const float* Wh = W + h * INF * OF;

    float acc[4][4] = {};
    for (int k0 = 0; k0 < INF; k0 += 16) {
        const int n = t >> 2, kq = (t & 3) * 4;
        float4 xv = *(const float4*)(x + (n0 + n) * INF + k0 + kq);
        const int kk = t & 15, f4 = t >> 4;
        float4 wv = *(const float4*)(Wh + (kk + k0) * OF + f4 * 4);
        __syncthreads();
        sx[kq + 0][n] = xv.x; sx[kq + 1][n] = xv.y;
        sx[kq + 2][n] = xv.z; sx[kq + 3][n] = xv.w;
        *(float4*)&sw[kk][f4 * 4] = wv;
        __syncthreads();
        #pragma unroll
        for (int k = 0; k < 16; k++) {
            float4 av = *(float4*)&sx[k][ty * 4];
            float4 bv = *(float4*)&sw[k][tx * 4];
            acc[0][0] += av.x * bv.x; acc[0][1] += av.x * bv.y; acc[0][2] += av.x * bv.z; acc[0][3] += av.x * bv.w;
            acc[1][0] += av.y * bv.x; acc[1][1] += av.y * bv.y; acc[1][2] += av.y * bv.z; acc[1][3] += av.y * bv.w;
            acc[2][0] += av.z * bv.x; acc[2][1] += av.z * bv.y; acc[2][2] += av.z * bv.z; acc[2][3] += av.z * bv.w;
            acc[3][0] += av.w * bv.x; acc[3][1] += av.w * bv.y; acc[3][2] += av.w * bv.z; acc[3][3] += av.w * bv.w;
        }
    }
    __syncthreads();
    #pragma unroll
    for (int r = 0; r < 4; r++)
        *(float4*)&sxt[ty * 4 + r][tx * 4] = make_float4(acc[r][0], acc[r][1], acc[r][2], acc[r][3]);
    __syncthreads();

    char* tb = g_Vt + (size_t)(h * 64 + blockIdx.x) * VCH;

    {
        const int row = t >> 2, qq = t & 3;
        const float* ah = a + h * 2 * OF;
        float s = 0.f, d = 0.f;
        #pragma unroll
        for (int ff = 0; ff < 16; ff++) {
            int f = qq * 16 + ff;
            float v = sxt[row][f];
            s += v * ah[f];
            d += v * ah[OF + f];
        }
        s += __shfl_xor_sync(0xffffffffu, s, 1); s += __shfl_xor_sync(0xffffffffu, s, 2);
        d += __shfl_xor_sync(0xffffffffu, d, 1); d += __shfl_xor_sync(0xffffffffu, d, 2);
        if (qq == 0) {
            g_idat[h][n0 + row] = make_float4(s, expf(s), expf(0.2f * s), 0.f);
            *(float*)(tb + 9216 + row * 4) = d;
            *(float*)(tb + 9472 + row * 4) = expf(d);
            *(float*)(tb + 9728 + row * 4) = expf(0.2f * d);
        }
    }
    __syncthreads();

    for (int idx = t; idx < 64 * 32; idx += 256) {
        int k = idx >> 5, u = idx & 31;
        int c0 = u * 2;
        __half2 hp = __floats2half2_rn(sxt[k][c0], sxt[k][c0 + 1]);
        *(uint32_t*)(tb + k * 144 + u * 4) = *(uint32_t*)&hp;
    }
}

// ---------------------------------------------------------------------------
// Kernel 3 (main): producer/consumer warp specialization, deep rings.
// 288 threads, 2 CTAs/SM: warps 0-3 consumers (mg2 x ng2, LDSM software-
// pipelined), warps 4-7 producers (j-quarter each), warp 8 TMA.
// W ring 4-deep, V ring 4-deep — producers/TMA run up to 4 chunks ahead.
// ---------------------------------------------------------------------------
#define SM_V   0                      // 4 x 10240 = 40960
#define SM_W   40960                  // 4 x 9216 = 36864
#define SM_Z   77824                  // 64 floats = 256B
#define SM_MB  78080                  // wfull[4] wfree[4] vfull[4] vfree[4]
#define SM_TOT 78208

__global__ __launch_bounds__(288, 2) void k_main(float* __restrict__ out) {
    extern __shared__ char smem[];
    const uint32_t sb = smem_u32(smem);
    const int h = blockIdx.y, i0 = blockIdx.x * 64;
    const int t = threadIdx.x, wid = t >> 5, lane = t & 31;
    const uint32_t wfull  = sb + SM_MB;        // 4 x 8B
    const uint32_t wfree  = sb + SM_MB + 32;   // 4 x 8B
    const uint32_t vfull  = sb + SM_MB + 64;   // 4 x 8B
    const uint32_t vfreeB = sb + SM_MB + 96;   // 4 x 8B
    float* zs = (float*)(smem + SM_Z);

    if (t == 0) {
        #pragma unroll
        for (int s = 0; s < 4; s++) {
            MBAR_INIT(wfull + s * 8, 128);
            MBAR_INIT(wfree + s * 8, 128);
            MBAR_INIT(vfull + s * 8, 1);
            MBAR_INIT(vfreeB + s * 8, 256);
        }
    }
    if (t < 64) zs[t] = 0.f;
    __syncthreads();

    if (wid == 8) {
        // ----------------------------- TMA warp -----------------------------
        if (lane == 0) {
            #pragma unroll 1
            for (int m = 0; m < 64; m++) {
                const int slot = m & 3;
                if (m >= 4) MBAR_WAIT(vfreeB + slot * 8, ((m - 4) >> 2) & 1);
                asm volatile("mbarrier.arrive.expect_tx.shared.b64 _, [%0], %1;"
                             :: "r"(vfull + slot * 8), "r"((uint32_t)VCH) : "memory");
                const char* src = g_Vt + (size_t)(h * 64 + m) * VCH;
                uint64_t sg; asm("cvta.to.global.u64 %0, %1;" : "=l"(sg) : "l"(src));
                asm volatile("cp.async.bulk.shared::cluster.global.mbarrier::complete_tx::bytes "
                             "[%0], [%1], %2, [%3];"
                             :: "r"(sb + SM_V + slot * VCH), "l"(sg), "r"((uint32_t)VCH),
                                "r"(vfull + slot * 8) : "memory");
            }
        }
    } else if (wid >= 4) {
        // ------------------------- 4 producer warps -------------------------
        const int q = wid - 4;                // j-quarter
        const int r0 = lane, r1 = lane + 32;
        const float4 id0 = g_idat[h][i0 + r0];
        const float4 id1 = g_idat[h][i0 + r1];
        const float th0 = -id0.x, A10 = id0.y, A20 = id0.z;
        const float th1 = -id1.x, A11 = id1.y, A21 = id1.z;
        float z0 = 0.f, z1 = 0.f;

        unsigned wc0 = g_adjT[q >> 1][i0 + r0] >> ((q & 1) * 16);
        unsigned wc1 = g_adjT[q >> 1][i0 + r1] >> ((q & 1) * 16);

        #pragma unroll 1
        for (int m = 0; m < 64; m++) {
            const int slot = m & 3;
            // prefetch next adjacency words (latency hidden under stage A)
            unsigned wn0 = 0, wn1 = 0;
            if (m < 63) {
                wn0 = g_adjT[(m + 1) * 2 + (q >> 1)][i0 + r0] >> ((q & 1) * 16);
                wn1 = g_adjT[(m + 1) * 2 + (q >> 1)][i0 + r1] >> ((q & 1) * 16);
            }
            MBAR_WAIT(vfull + slot * 8, (m >> 2) & 1);               // tile m tail
            if (m >= 4) MBAR_WAIT(wfree + slot * 8, ((m - 4) >> 2) & 1);

            const char* jb = smem + SM_V + slot * VCH + 9216 + q * 64;
            uint32_t vv0[8], vv1[8];
            #pragma unroll
            for (int u = 0; u < 4; u++) {
                float4 f0 = *(const float4*)(jb + u * 16);          // dst
                float4 f1 = *(const float4*)(jb + 256 + u * 16);    // e1
                float4 f2 = *(const float4*)(jb + 512 + u * 16);    // e2
                float a0 = (f0.x >= th0) ? A10 * f1.x : A20 * f2.x;
                float a1 = (f0.y >= th0) ? A10 * f1.y : A20 * f2.y;
                float a2 = (f0.z >= th0) ? A10 * f1.z : A20 * f2.z;
                float a3 = (f0.w >= th0) ? A10 * f1.w : A20 * f2.w;
                a0 = ((wc0 >> (4 * u + 0)) & 1u) ? a0 : 0.f;
                a1 = ((wc0 >> (4 * u + 1)) & 1u) ? a1 : 0.f;
                a2 = ((wc0 >> (4 * u + 2)) & 1u) ? a2 : 0.f;
                a3 = ((wc0 >> (4 * u + 3)) & 1u) ? a3 : 0.f;
                z0 += (a0 + a1) + (a2 + a3);
                __half2 p0 = __floats2half2_rn(a0, a1);
                __half2 p1 = __floats2half2_rn(a2, a3);
                vv0[2 * u] = *(uint32_t*)&p0; vv0[2 * u + 1] = *(uint32_t*)&p1;
                float b0 = (f0.x >= th1) ? A11 * f1.x : A21 * f2.x;
                float b1 = (f0.y >= th1) ? A11 * f1.y : A21 * f2.y;
                float b2 = (f0.z >= th1) ? A11 * f1.z : A21 * f2.z;
                float b3 = (f0.w >= th1) ? A11 * f1.w : A21 * f2.w;
                b0 = ((wc1 >> (4 * u + 0)) & 1u) ? b0 : 0.f;
                b1 = ((wc1 >> (4 * u + 1)) & 1u) ? b1 : 0.f;
                b2 = ((wc1 >> (4 * u + 2)) & 1u) ? b2 : 0.f;
                b3 = ((wc1 >> (4 * u + 3)) & 1u) ? b3 : 0.f;
                z1 += (b0 + b1) + (b2 + b3);
                __half2 p2 = __floats2half2_rn(b0, b1);
                __half2 p3 = __floats2half2_rn(b2, b3);
                vv1[2 * u] = *(uint32_t*)&p2; vv1[2 * u + 1] = *(uint32_t*)&p3;
            }
            char* w_ = smem + SM_W + slot * 9216;
            char* pr0 = w_ + r0 * 144 + q * 32;
            char* pr1 = w_ + r1 * 144 + q * 32;
            *(uint4*)(pr0)      = make_uint4(vv0[0], vv0[1], vv0[2], vv0[3]);
            *(uint4*)(pr0 + 16) = make_uint4(vv0[4], vv0[5], vv0[6], vv0[7]);
            *(uint4*)(pr1)      = make_uint4(vv1[0], vv1[1], vv1[2], vv1[3]);
            *(uint4*)(pr1 + 16) = make_uint4(vv1[4], vv1[5], vv1[6], vv1[7]);

            MBAR_ARRIVE(wfull + slot * 8);        // all 128 producer threads
            MBAR_ARRIVE(vfreeB + slot * 8);       // producer release of tile m
            wc0 = wn0; wc1 = wn1;
        }
        atomicAdd(&zs[r0], z0);
        atomicAdd(&zs[r1], z1);
    } else {
        // ------------- 4 consumer warps (LDSM software-pipelined) -----------
        const int mgw = wid >> 1, ngw = wid & 1;
        const uint32_t aOff = (uint32_t)((mgw * 32 + (lane & 15)) * 144 + (lane >> 4) * 16);
        const uint32_t bO = (uint32_t)((lane & 15) * 144 + (lane >> 4) * 16 + ngw * 64);
        float d[2][4][4] = {};

        #pragma unroll 1
        for (int m = 0; m < 64; m++) {
            const int slot = m & 3;
            MBAR_WAIT(wfull + slot * 8, (m >> 2) & 1);
            MBAR_WAIT(vfull + slot * 8, (m >> 2) & 1);
            const uint32_t vb = sb + SM_V + slot * VCH;
            const uint32_t aW = sb + SM_W + slot * 9216 + aOff;

            uint32_t af[2][2][4], bA[2][4], bB[2][4];
            LDSM_X4(af[0][0], aW);
            LDSM_X4(af[0][1], aW + 2304);
            LDSM_X4T(bA[0], vb + bO);
            LDSM_X4T(bB[0], vb + bO + 32);
            #pragma unroll
            for (int ks = 0; ks < 4; ks++) {
                const int cur = ks & 1, nxt = cur ^ 1;
                if (ks < 3) {
                    const uint32_t kb = vb + (uint32_t)(ks + 1) * 2304;
                    LDSM_X4(af[nxt][0], aW + (ks + 1) * 32);
                    LDSM_X4(af[nxt][1], aW + 2304 + (ks + 1) * 32);
                    LDSM_X4T(bA[nxt], kb + bO);
                    LDSM_X4T(bB[nxt], kb + bO + 32);
                }
                MMA(d[0][0], af[cur][0], bA[cur][0], bA[cur][1]);
                MMA(d[0][1], af[cur][0], bA[cur][2], bA[cur][3]);
                MMA(d[0][2], af[cur][0], bB[cur][0], bB[cur][1]);
                MMA(d[0][3], af[cur][0], bB[cur][2], bB[cur][3]);
                MMA(d[1][0], af[cur][1], bA[cur][0], bA[cur][1]);
                MMA(d[1][1], af[cur][1], bA[cur][2], bA[cur][3]);
                MMA(d[1][2], af[cur][1], bB[cur][0], bB[cur][1]);
                MMA(d[1][3], af[cur][1], bB[cur][2], bB[cur][3]);
            }
            MBAR_ARRIVE(wfree + slot * 8);        // all 128 consumer threads
            MBAR_ARRIVE(vfreeB + slot * 8);       // consumer release of tile m
        }

        __syncthreads();   // join with producers' zs atomics
        #pragma unroll
        for (int mt = 0; mt < 2; mt++) {
            int rlo = mgw * 32 + mt * 16 + (lane >> 2);
            int rhi = rlo + 8;
            float zlo = 1.0f / zs[rlo];
            float zhi = 1.0f / zs[rhi];
            #pragma unroll
            for (int nt = 0; nt < 4; nt++) {
                int col = h * OF + ngw * 32 + nt * 8 + (lane & 3) * 2;
                float* dd = d[mt][nt];
                float2 plo = make_float2(dd[0] * zlo, dd[1] * zlo);
                float2 phi = make_float2(dd[2] * zhi, dd[3] * zhi);
                *(float2*)(out + (size_t)(i0 + rlo) * (NH * OF) + col) = plo;
                *(float2*)(out + (size_t)(i0 + rhi) * (NH * OF) + col) = phi;
            }
        }
        return;
    }
    __syncthreads();   // producers + TMA warp join the epilogue barrier
}

// ---------------------------------------------------------------------------
extern "C" void kernel_launch(void* const* d_in, const int* in_sizes, int n_in,
                              void* d_out, int out_size) {
    const float* x   = (const float*)d_in[0];  // [4096, 256]
    const float* W   = (const float*)d_in[1];  // [4, 256, 64]
    const float* a   = (const float*)d_in[2];  // [4, 128]
    const int*   adj = (const int*)d_in[3];    // [4096, 4096]
    float* out = (float*)d_out;                // [4096, 256]
    (void)in_sizes; (void)n_in; (void)out_size;

    cudaFuncSetAttribute(k_main, cudaFuncAttributeMaxDynamicSharedMemorySize, SM_TOT);

    k_bitpack<<<(NN * NN / 16) / 256, 256>>>(adj);
    k_xtv<<<dim3(NN / 64, NH), 256>>>(x, W, a);
    k_main<<<dim3(NN / 64, NH), 288, SM_TOT>>>(out);
}

// round 14
// speedup vs baseline: 1.0728x; 1.0728x over previous
#include <cuda_runtime.h>
#include <cuda_fp16.h>
#include <cstdint>

#define NN 4096
#define INF 256
#define OF 64
#define NH 4

// ---------------------------------------------------------------------------
// Scratch globals
// ---------------------------------------------------------------------------
__device__ float4   g_idat[NH][NN];        // {src, exp(src), exp(0.2*src), 0}
__device__ unsigned g_adjT[NN / 32][NN];   // adjacency bits [wordcol][row]
// xt tiles: per (h,chunk): fp16 seg [64 k][64 n] (rows 144B) + 1KB tail:
//   [9216,9472) dst f32[64]   [9472,9728) e1 f32[64]   [9728,9984) e2 f32[64]
#define SEGB 9216
#define VCH  10240
__device__ __align__(16) char g_Vt[NH * 64 * VCH];

// ---------------------------------------------------------------------------
// PTX helpers (family-generic: no tcgen05 on compute_103 virtual target)
// ---------------------------------------------------------------------------
__device__ __forceinline__ uint32_t smem_u32(const void* p) {
    uint32_t a;
    asm("{ .reg .u64 t; cvta.to.shared.u64 t, %1; cvt.u32.u64 %0, t; }" : "=r"(a) : "l"(p));
    return a;
}
#define MBAR_INIT(a, n) asm volatile("mbarrier.init.shared.b64 [%0], %1;" :: "r"(a), "r"(n) : "memory")
#define MBAR_WAIT(a, ph) do {                                                            \
    uint32_t _m = (a), _p = (ph), _d;                                                    \
    asm volatile("{ .reg .pred p; mbarrier.try_wait.parity.acquire.cta.shared::cta.b64 " \
                 "p, [%1], %2; selp.b32 %0, 1, 0, p; }" : "=r"(_d) : "r"(_m), "r"(_p) : "memory"); \
    if (!_d) {                                                                           \
        asm volatile("{ .reg .pred P1; WL_%=: mbarrier.try_wait.parity.acquire.cta.shared::cta.b64 " \
                     "P1, [%0], %1, 0x989680; @P1 bra.uni WD_%=; bra.uni WL_%=; WD_%=: }" \
                     :: "r"(_m), "r"(_p) : "memory");                                    \
    }                                                                                    \
} while (0)
#define BAR_SYNC(id, n)   asm volatile("bar.sync %0, %1;"   :: "r"(id), "r"(n) : "memory")
#define BAR_ARRIVE(id, n) asm volatile("bar.arrive %0, %1;" :: "r"(id), "r"(n) : "memory")

#define LDSM_X4(r, a)                                                         \
    asm volatile("ldmatrix.sync.aligned.m8n8.x4.shared.b16 {%0,%1,%2,%3}, [%4];" \
        : "=r"((r)[0]), "=r"((r)[1]), "=r"((r)[2]), "=r"((r)[3]) : "r"(a))
#define LDSM_X4T(r, a)                                                        \
    asm volatile("ldmatrix.sync.aligned.m8n8.x4.trans.shared.b16 {%0,%1,%2,%3}, [%4];" \
        : "=r"((r)[0]), "=r"((r)[1]), "=r"((r)[2]), "=r"((r)[3]) : "r"(a))

#define MMA(d, a, b0_, b1_)                                                   \
    asm volatile("mma.sync.aligned.m16n8k16.row.col.f32.f16.f16.f32 "         \
        "{%0,%1,%2,%3},{%4,%5,%6,%7},{%8,%9},{%0,%1,%2,%3};"                  \
        : "+f"((d)[0]), "+f"((d)[1]), "+f"((d)[2]), "+f"((d)[3])              \
        : "r"((a)[0]), "r"((a)[1]), "r"((a)[2]), "r"((a)[3]), "r"(b0_), "r"(b1_))

// ---------------------------------------------------------------------------
// Kernel 1: adjacency bitpack (transposed), 16 elements/thread (measured best)
// ---------------------------------------------------------------------------
__global__ __launch_bounds__(256) void k_bitpack(const int* __restrict__ adj) {
    size_t tid = (size_t)blockIdx.x * 256 + threadIdx.x;
    int lane = threadIdx.x & 31;
    size_t base = tid * 16;
    int row = (int)(base >> 12), col = (int)(base & 4095);
    unsigned bits = 0;
    #pragma unroll
    for (int e = 0; e < 4; e++) {
        int4 v = *(const int4*)(adj + (size_t)row * NN + col + e * 4);
        bits |= ((unsigned)(v.x > 0) << (e * 4)) | ((unsigned)(v.y > 0) << (e * 4 + 1)) |
                ((unsigned)(v.z > 0) << (e * 4 + 2)) | ((unsigned)(v.w > 0) << (e * 4 + 3));
    }
    unsigned val = bits << (((unsigned)(col >> 4) & 1u) * 16u);
    val |= __shfl_xor_sync(0xffffffffu, val, 1);
    if ((lane & 1) == 0) g_adjT[col >> 5][row] = val;
}

// ---------------------------------------------------------------------------
// Kernel 2: xt GEMM + per-row scalars + fp16 xt-tile build (j-data in tail).
// ---------------------------------------------------------------------------
__global__ __launch_bounds__(256) void k_xtv(const float* __restrict__ x,
                                             const float* __restrict__ W,
                                             const float* __restrict__ a) {
    __shared__ float sx[16][68];
    __shared__ float sw[16][64];
    __shared__ float sxt[64][68];
    const int h = blockIdx.y, n0 = blockIdx.x * 64, t = threadIdx.x;
    const int tx = t & 15, ty = t >> 4;
    const float* Wh = W + h * INF * OF;

    float acc[4][4] = {};
    for (int k0 = 0; k0 < INF; k0 += 16) {
        const int n = t >> 2, kq = (t & 3) * 4;
        float4 xv = *(const float4*)(x + (n0 + n) * INF + k0 + kq);
        const int kk = t & 15, f4 = t >> 4;
        float4 wv = *(const float4*)(Wh + (kk + k0) * OF + f4 * 4);
        __syncthreads();
        sx[kq + 0][n] = xv.x; sx[kq + 1][n] = xv.y;
        sx[kq + 2][n] = xv.z; sx[kq + 3][n] = xv.w;
        *(float4*)&sw[kk][f4 * 4] = wv;
        __syncthreads();
        #pragma unroll
        for (int k = 0; k < 16; k++) {
            float4 av = *(float4*)&sx[k][ty * 4];
            float4 bv = *(float4*)&sw[k][tx * 4];
            acc[0][0] += av.x * bv.x; acc[0][1] += av.x * bv.y; acc[0][2] += av.x * bv.z; acc[0][3] += av.x * bv.w;
            acc[1][0] += av.y * bv.x; acc[1][1] += av.y * bv.y; acc[1][2] += av.y * bv.z; acc[1][3] += av.y * bv.w;
            acc[2][0] += av.z * bv.x; acc[2][1] += av.z * bv.y; acc[2][2] += av.z * bv.z; acc[2][3] += av.z * bv.w;
            acc[3][0] += av.w * bv.x; acc[3][1] += av.w * bv.y; acc[3][2] += av.w * bv.z; acc[3][3] += av.w * bv.w;
        }
    }
    __syncthreads();
    #pragma unroll
    for (int r = 0; r < 4; r++)
        *(float4*)&sxt[ty * 4 + r][tx * 4] = make_float4(acc[r][0], acc[r][1], acc[r][2], acc[r][3]);
    __syncthreads();

    char* tb = g_Vt + (size_t)(h * 64 + blockIdx.x) * VCH;

    {
        const int row = t >> 2, qq = t & 3;
        const float* ah = a + h * 2 * OF;
        float s = 0.f, d = 0.f;
        #pragma unroll
        for (int ff = 0; ff < 16; ff++) {
            int f = qq * 16 + ff;
            float v = sxt[row][f];
            s += v * ah[f];
            d += v * ah[OF + f];
        }
        s += __shfl_xor_sync(0xffffffffu, s, 1); s += __shfl_xor_sync(0xffffffffu, s, 2);
        d += __shfl_xor_sync(0xffffffffu, d, 1); d += __shfl_xor_sync(0xffffffffu, d, 2);
        if (qq == 0) {
            g_idat[h][n0 + row] = make_float4(s, expf(s), expf(0.2f * s), 0.f);
            *(float*)(tb + 9216 + row * 4) = d;
            *(float*)(tb + 9472 + row * 4) = expf(d);
            *(float*)(tb + 9728 + row * 4) = expf(0.2f * d);
        }
    }
    __syncthreads();

    for (int idx = t; idx < 64 * 32; idx += 256) {
        int k = idx >> 5, u = idx & 31;
        int c0 = u * 2;
        __half2 hp = __floats2half2_rn(sxt[k][c0], sxt[k][c0 + 1]);
        *(uint32_t*)(tb + k * 144 + u * 4) = *(uint32_t*)&hp;
    }
}

// ---------------------------------------------------------------------------
// Kernel 3 (main): warp-specialized, named-barrier handoffs (BAR not ATOMS).
// 288 threads, 2 CTAs/SM: warps 0-3 consumers, 4-7 producers, 8 TMA.
// W ring 4-deep, V ring 4-deep. Barriers:
//   wfull[slot] = id 1+slot  (256: producers arrive, consumers sync)
//   wfree[slot] = id 5+slot  (256: consumers arrive, producers sync, skip m<4)
//   vfree[slot] = id 9+slot  (288: prod+cons arrive, TMA warp syncs, skip m<4)
// Only vfull stays an mbarrier (TMA complete_tx), waited by producers only;
// consumers inherit V readiness transitively through wfull.
// ---------------------------------------------------------------------------
#define SM_V   0                      // 4 x 10240 = 40960
#define SM_W   40960                  // 4 x 9216 = 36864
#define SM_Z   77824                  // 64 floats = 256B
#define SM_MB  78080                  // vfull[4]
#define SM_TOT 78144

__global__ __launch_bounds__(288, 2) void k_main(float* __restrict__ out) {
    extern __shared__ char smem[];
    const uint32_t sb = smem_u32(smem);
    const int h = blockIdx.y, i0 = blockIdx.x * 64;
    const int t = threadIdx.x, wid = t >> 5, lane = t & 31;
    const uint32_t vfull = sb + SM_MB;        // 4 x 8B
    float* zs = (float*)(smem + SM_Z);

    if (t == 0) {
        #pragma unroll
        for (int s = 0; s < 4; s++) MBAR_INIT(vfull + s * 8, 1);
    }
    if (t < 64) zs[t] = 0.f;
    __syncthreads();

    if (wid == 8) {
        // ----------------------------- TMA warp -----------------------------
        #pragma unroll 1
        for (int m = 0; m < 64; m++) {
            const int slot = m & 3;
            if (m >= 4) BAR_SYNC(9 + slot, 288);        // V[slot] fully released
            if (lane == 0) {
                asm volatile("mbarrier.arrive.expect_tx.shared.b64 _, [%0], %1;"
                             :: "r"(vfull + slot * 8), "r"((uint32_t)VCH) : "memory");
                const char* src = g_Vt + (size_t)(h * 64 + m) * VCH;
                uint64_t sg; asm("cvta.to.global.u64 %0, %1;" : "=l"(sg) : "l"(src));
                asm volatile("cp.async.bulk.shared::cluster.global.mbarrier::complete_tx::bytes "
                             "[%0], [%1], %2, [%3];"
                             :: "r"(sb + SM_V + slot * VCH), "l"(sg), "r"((uint32_t)VCH),
                                "r"(vfull + slot * 8) : "memory");
            }
        }
    } else if (wid >= 4) {
        // ------------------------- 4 producer warps -------------------------
        const int q = wid - 4;                // j-quarter
        const int r0 = lane, r1 = lane + 32;
        const float4 id0 = g_idat[h][i0 + r0];
        const float4 id1 = g_idat[h][i0 + r1];
        const float th0 = -id0.x, A10 = id0.y, A20 = id0.z;
        const float th1 = -id1.x, A11 = id1.y, A21 = id1.z;
        float z0 = 0.f, z1 = 0.f;

        unsigned wc0 = g_adjT[q >> 1][i0 + r0] >> ((q & 1) * 16);
        unsigned wc1 = g_adjT[q >> 1][i0 + r1] >> ((q & 1) * 16);

        #pragma unroll 1
        for (int m = 0; m < 64; m++) {
            const int slot = m & 3;
            unsigned wn0 = 0, wn1 = 0;
            if (m < 63) {
                wn0 = g_adjT[(m + 1) * 2 + (q >> 1)][i0 + r0] >> ((q & 1) * 16);
                wn1 = g_adjT[(m + 1) * 2 + (q >> 1)][i0 + r1] >> ((q & 1) * 16);
            }
            MBAR_WAIT(vfull + slot * 8, (m >> 2) & 1);  // V tile m (acquire)
            if (m >= 4) BAR_SYNC(5 + slot, 256);        // W[slot] free

            const char* jb = smem + SM_V + slot * VCH + 9216 + q * 64;
            uint32_t vv0[8], vv1[8];
            #pragma unroll
            for (int u = 0; u < 4; u++) {
                float4 f0 = *(const float4*)(jb + u * 16);          // dst
                float4 f1 = *(const float4*)(jb + 256 + u * 16);    // e1
                float4 f2 = *(const float4*)(jb + 512 + u * 16);    // e2
                float a0 = (f0.x >= th0) ? A10 * f1.x : A20 * f2.x;
                float a1 = (f0.y >= th0) ? A10 * f1.y : A20 * f2.y;
                float a2 = (f0.z >= th0) ? A10 * f1.z : A20 * f2.z;
                float a3 = (f0.w >= th0) ? A10 * f1.w : A20 * f2.w;
                a0 = ((wc0 >> (4 * u + 0)) & 1u) ? a0 : 0.f;
                a1 = ((wc0 >> (4 * u + 1)) & 1u) ? a1 : 0.f;
                a2 = ((wc0 >> (4 * u + 2)) & 1u) ? a2 : 0.f;
                a3 = ((wc0 >> (4 * u + 3)) & 1u) ? a3 : 0.f;
                z0 += (a0 + a1) + (a2 + a3);
                __half2 p0 = __floats2half2_rn(a0, a1);
                __half2 p1 = __floats2half2_rn(a2, a3);
                vv0[2 * u] = *(uint32_t*)&p0; vv0[2 * u + 1] = *(uint32_t*)&p1;
                float b0 = (f0.x >= th1) ? A11 * f1.x : A21 * f2.x;
                float b1 = (f0.y >= th1) ? A11 * f1.y : A21 * f2.y;
                float b2 = (f0.z >= th1) ? A11 * f1.z : A21 * f2.z;
                float b3 = (f0.w >= th1) ? A11 * f1.w : A21 * f2.w;
                b0 = ((wc1 >> (4 * u + 0)) & 1u) ? b0 : 0.f;
                b1 = ((wc1 >> (4 * u + 1)) & 1u) ? b1 : 0.f;
                b2 = ((wc1 >> (4 * u + 2)) & 1u) ? b2 : 0.f;
                b3 = ((wc1 >> (4 * u + 3)) & 1u) ? b3 : 0.f;
                z1 += (b0 + b1) + (b2 + b3);
                __half2 p2 = __floats2half2_rn(b0, b1);
                __half2 p3 = __floats2half2_rn(b2, b3);
                vv1[2 * u] = *(uint32_t*)&p2; vv1[2 * u + 1] = *(uint32_t*)&p3;
            }
            char* w_ = smem + SM_W + slot * 9216;
            char* pr0 = w_ + r0 * 144 + q * 32;
            char* pr1 = w_ + r1 * 144 + q * 32;
            *(uint4*)(pr0)      = make_uint4(vv0[0], vv0[1], vv0[2], vv0[3]);
            *(uint4*)(pr0 + 16) = make_uint4(vv0[4], vv0[5], vv0[6], vv0[7]);
            *(uint4*)(pr1)      = make_uint4(vv1[0], vv1[1], vv1[2], vv1[3]);
            *(uint4*)(pr1 + 16) = make_uint4(vv1[4], vv1[5], vv1[6], vv1[7]);

            BAR_ARRIVE(1 + slot, 256);          // W[slot] full (drains STS)
            BAR_ARRIVE(9 + slot, 288);          // done reading V[slot] tail
            wc0 = wn0; wc1 = wn1;
        }
        atomicAdd(&zs[r0], z0);
        atomicAdd(&zs[r1], z1);
    } else {
        // ------------- 4 consumer warps (LDSM software-pipelined) -----------
        const int mgw = wid >> 1, ngw = wid & 1;
        const uint32_t aOff = (uint32_t)((mgw * 32 + (lane & 15)) * 144 + (lane >> 4) * 16);
        const uint32_t bO = (uint32_t)((lane & 15) * 144 + (lane >> 4) * 16 + ngw * 64);
        float d[2][4][4] = {};

        #pragma unroll 1
        for (int m = 0; m < 64; m++) {
            const int slot = m & 3;
            BAR_SYNC(1 + slot, 256);            // W[slot] + V[slot] ready
            const uint32_t vb = sb + SM_V + slot * VCH;
            const uint32_t aW = sb + SM_W + slot * 9216 + aOff;

            uint32_t af[2][2][4], bA[2][4], bB[2][4];
            LDSM_X4(af[0][0], aW);
            LDSM_X4(af[0][1], aW + 2304);
            LDSM_X4T(bA[0], vb + bO);
            LDSM_X4T(bB[0], vb + bO + 32);
            #pragma unroll
            for (int ks = 0; ks < 4; ks++) {
                const int cur = ks & 1, nxt = cur ^ 1;
                if (ks < 3) {
                    const uint32_t kb = vb + (uint32_t)(ks + 1) * 2304;
                    LDSM_X4(af[nxt][0], aW + (ks + 1) * 32);
                    LDSM_X4(af[nxt][1], aW + 2304 + (ks + 1) * 32);
                    LDSM_X4T(bA[nxt], kb + bO);
                    LDSM_X4T(bB[nxt], kb + bO + 32);
                }
                MMA(d[0][0], af[cur][0], bA[cur][0], bA[cur][1]);
                MMA(d[0][1], af[cur][0], bA[cur][2], bA[cur][3]);
                MMA(d[0][2], af[cur][0], bB[cur][0], bB[cur][1]);
                MMA(d[0][3], af[cur][0], bB[cur][2], bB[cur][3]);
                MMA(d[1][0], af[cur][1], bA[cur][0], bA[cur][1]);
                MMA(d[1][1], af[cur][1], bA[cur][2], bA[cur][3]);
                MMA(d[1][2], af[cur][1], bB[cur][0], bB[cur][1]);
                MMA(d[1][3], af[cur][1], bB[cur][2], bB[cur][3]);
            }
            BAR_ARRIVE(5 + slot, 256);          // release W[slot]
            BAR_ARRIVE(9 + slot, 288);          // release V[slot]
        }

        __syncthreads();   // join with producers' zs atomics
        #pragma unroll
        for (int mt = 0; mt < 2; mt++) {
            int rlo = mgw * 32 + mt * 16 + (lane >> 2);
            int rhi = rlo + 8;
            float zlo = 1.0f / zs[rlo];
            float zhi = 1.0f / zs[rhi];
            #pragma unroll
            for (int nt = 0; nt < 4; nt++) {
                int col = h * OF + ngw * 32 + nt * 8 + (lane & 3) * 2;
                float* dd = d[mt][nt];
                float2 plo = make_float2(dd[0] * zlo, dd[1] * zlo);
                float2 phi = make_float2(dd[2] * zhi, dd[3] * zhi);
                *(float2*)(out + (size_t)(i0 + rlo) * (NH * OF) + col) = plo;
                *(float2*)(out + (size_t)(i0 + rhi) * (NH * OF) + col) = phi;
            }
        }
        return;
    }
    __syncthreads();   // producers + TMA warp join the epilogue barrier
}

// ---------------------------------------------------------------------------
extern "C" void kernel_launch(void* const* d_in, const int* in_sizes, int n_in,
                              void* d_out, int out_size) {
    const float* x   = (const float*)d_in[0];  // [4096, 256]
    const float* W   = (const float*)d_in[1];  // [4, 256, 64]
    const float* a   = (const float*)d_in[2];  // [4, 128]
    const int*   adj = (const int*)d_in[3];    // [4096, 4096]
    float* out = (float*)d_out;                // [4096, 256]
    (void)in_sizes; (void)n_in; (void)out_size;

    cudaFuncSetAttribute(k_main, cudaFuncAttributeMaxDynamicSharedMemorySize, SM_TOT);

    k_bitpack<<<(NN * NN / 16) / 256, 256>>>(adj);
    k_xtv<<<dim3(NN / 64, NH), 256>>>(x, W, a);
    k_main<<<dim3(NN / 64, NH), 288, SM_TOT>>>(out);
}

// round 16
// speedup vs baseline: 1.0756x; 1.0027x over previous
#include <cuda_runtime.h>
#include <cuda_fp16.h>
#include <cstdint>

#define NN 4096
#define INF 256
#define OF 64
#define NH 4

// ---------------------------------------------------------------------------
// Scratch globals
// ---------------------------------------------------------------------------
__device__ float4   g_idat[NH][NN];        // {src, exp(src), exp(0.2*src), 0}
__device__ unsigned g_adjT[NN / 32][NN];   // adjacency bits [wordcol][row]
// xt tiles: per (h,chunk): fp16 seg [64 k][64 n] (rows 144B) + 1KB tail:
//   [9216,9472) dst f32[64]   [9472,9728) e1 f32[64]   [9728,9984) e2 f32[64]
#define SEGB 9216
#define VCH  10240
__device__ __align__(16) char g_Vt[NH * 64 * VCH];

// ---------------------------------------------------------------------------
// PTX helpers (family-generic: no tcgen05 on compute_103 virtual target)
// ---------------------------------------------------------------------------
__device__ __forceinline__ uint32_t smem_u32(const void* p) {
    uint32_t a;
    asm("{ .reg .u64 t; cvta.to.shared.u64 t, %1; cvt.u32.u64 %0, t; }" : "=r"(a) : "l"(p));
    return a;
}
#define MBAR_INIT(a, n) asm volatile("mbarrier.init.shared.b64 [%0], %1;" :: "r"(a), "r"(n) : "memory")
#define MBAR_WAIT(a, ph) do {                                                            \
    uint32_t _m = (a), _p = (ph), _d;                                                    \
    asm volatile("{ .reg .pred p; mbarrier.try_wait.parity.acquire.cta.shared::cta.b64 " \
                 "p, [%1], %2; selp.b32 %0, 1, 0, p; }" : "=r"(_d) : "r"(_m), "r"(_p) : "memory"); \
    if (!_d) {                                                                           \
        asm volatile("{ .reg .pred P1; WL_%=: mbarrier.try_wait.parity.acquire.cta.shared::cta.b64 " \
                     "P1, [%0], %1, 0x989680; @P1 bra.uni WD_%=; bra.uni WL_%=; WD_%=: }" \
                     :: "r"(_m), "r"(_p) : "memory");                                    \
    }                                                                                    \
} while (0)
#define BAR_SYNC(id, n)   asm volatile("bar.sync %0, %1;"   :: "r"(id), "r"(n) : "memory")
#define BAR_ARRIVE(id, n) asm volatile("bar.arrive %0, %1;" :: "r"(id), "r"(n) : "memory")

#define LDSM_X4(r, a)                                                         \
    asm volatile("ldmatrix.sync.aligned.m8n8.x4.shared.b16 {%0,%1,%2,%3}, [%4];" \
        : "=r"((r)[0]), "=r"((r)[1]), "=r"((r)[2]), "=r"((r)[3]) : "r"(a))
#define LDSM_X4T(r, a)                                                        \
    asm volatile("ldmatrix.sync.aligned.m8n8.x4.trans.shared.b16 {%0,%1,%2,%3}, [%4];" \
        : "=r"((r)[0]), "=r"((r)[1]), "=r"((r)[2]), "=r"((r)[3]) : "r"(a))

#define MMA(d, a, b0_, b1_)                                                   \
    asm volatile("mma.sync.aligned.m16n8k16.row.col.f32.f16.f16.f32 "         \
        "{%0,%1,%2,%3},{%4,%5,%6,%7},{%8,%9},{%0,%1,%2,%3};"                  \
        : "+f"((d)[0]), "+f"((d)[1]), "+f"((d)[2]), "+f"((d)[3])              \
        : "r"((a)[0]), "r"((a)[1]), "r"((a)[2]), "r"((a)[3]), "r"(b0_), "r"(b1_))

// ---------------------------------------------------------------------------
// Kernel 1: adjacency bitpack (transposed), 16 elements/thread (measured best)
// ---------------------------------------------------------------------------
__global__ __launch_bounds__(256) void k_bitpack(const int* __restrict__ adj) {
    size_t tid = (size_t)blockIdx.x * 256 + threadIdx.x;
    int lane = threadIdx.x & 31;
    size_t base = tid * 16;
    int row = (int)(base >> 12), col = (int)(base & 4095);
    unsigned bits = 0;
    #pragma unroll
    for (int e = 0; e < 4; e++) {
        int4 v = *(const int4*)(adj + (size_t)row * NN + col + e * 4);
        bits |= ((unsigned)(v.x > 0) << (e * 4)) | ((unsigned)(v.y > 0) << (e * 4 + 1)) |
                ((unsigned)(v.z > 0) << (e * 4 + 2)) | ((unsigned)(v.w > 0) << (e * 4 + 3));
    }
    unsigned val = bits << (((unsigned)(col >> 4) & 1u) * 16u);
    val |= __shfl_xor_sync(0xffffffffu, val, 1);
    if ((lane & 1) == 0) g_adjT[col >> 5][row] = val;
}

// ---------------------------------------------------------------------------
// Kernel 2: xt GEMM + per-row scalars + fp16 xt-tile build (j-data in tail).
// ---------------------------------------------------------------------------
__global__ __launch_bounds__(256) void k_xtv(const float* __restrict__ x,
                                             const float* __restrict__ W,
                                             const float* __restrict__ a) {
    __shared__ float sx[16][68];
    __shared__ float sw[16][64];
    __shared__ float sxt[64][68];
    const int h = blockIdx.y, n0 = blockIdx.x * 64, t = threadIdx.x;
    const int tx = t & 15, ty = t >> 4;
    const float* Wh = W + h * INF * OF;

    float acc[4][4] = {};
    for (int k0 = 0; k0 < INF; k0 += 16) {
        const int n = t >> 2, kq = (t & 3) * 4;
        float4 xv = *(const float4*)(x + (n0 + n) * INF + k0 + kq);
        const int kk = t & 15, f4 = t >> 4;
        float4 wv = *(const float4*)(Wh + (kk + k0) * OF + f4 * 4);
        __syncthreads();
        sx[kq + 0][n] = xv.x; sx[kq + 1][n] = xv.y;
        sx[kq + 2][n] = xv.z; sx[kq + 3][n] = xv.w;
        *(float4*)&sw[kk][f4 * 4] = wv;
        __syncthreads();
        #pragma unroll
        for (int k = 0; k < 16; k++) {
            float4 av = *(float4*)&sx[k][ty * 4];
            float4 bv = *(float4*)&sw[k][tx * 4];
            acc[0][0] += av.x * bv.x; acc[0][1] += av.x * bv.y; acc[0][2] += av.x * bv.z; acc[0][3] += av.x * bv.w;
            acc[1][0] += av.y * bv.x; acc[1][1] += av.y * bv.y; acc[1][2] += av.y * bv.z; acc[1][3] += av.y * bv.w;
            acc[2][0] += av.z * bv.x; acc[2][1] += av.z * bv.y; acc[2][2] += av.z * bv.z; acc[2][3] += av.z * bv.w;
            acc[3][0] += av.w * bv.x; acc[3][1] += av.w * bv.y; acc[3][2] += av.w * bv.z; acc[3][3] += av.w * bv.w;
        }
    }
    __syncthreads();
    #pragma unroll
    for (int r = 0; r < 4; r++)
        *(float4*)&sxt[ty * 4 + r][tx * 4] = make_float4(acc[r][0], acc[r][1], acc[r][2], acc[r][3]);
    __syncthreads();

    char* tb = g_Vt + (size_t)(h * 64 + blockIdx.x) * VCH;

    {
        const int row = t >> 2, qq = t & 3;
        const float* ah = a + h * 2 * OF;
        float s = 0.f, d = 0.f;
        #pragma unroll
        for (int ff = 0; ff < 16; ff++) {
            int f = qq * 16 + ff;
            float v = sxt[row][f];
            s += v * ah[f];
            d += v * ah[OF + f];
        }
        s += __shfl_xor_sync(0xffffffffu, s, 1); s += __shfl_xor_sync(0xffffffffu, s, 2);
        d += __shfl_xor_sync(0xffffffffu, d, 1); d += __shfl_xor_sync(0xffffffffu, d, 2);
        if (qq == 0) {
            g_idat[h][n0 + row] = make_float4(s, expf(s), expf(0.2f * s), 0.f);
            *(float*)(tb + 9216 + row * 4) = d;
            *(float*)(tb + 9472 + row * 4) = expf(d);
            *(float*)(tb + 9728 + row * 4) = expf(0.2f * d);
        }
    }
    __syncthreads();

    for (int idx = t; idx < 64 * 32; idx += 256) {
        int k = idx >> 5, u = idx & 31;
        int c0 = u * 2;
        __half2 hp = __floats2half2_rn(sxt[k][c0], sxt[k][c0 + 1]);
        *(uint32_t*)(tb + k * 144 + u * 4) = *(uint32_t*)&hp;
    }
}

// ---------------------------------------------------------------------------
// Kernel 3 (main): warp-specialized, double-chunk epochs (32 epochs x K=128).
// 288 threads, 2 CTAs/SM: warps 0-3 consumers, 4-7 producers, 8 TMA.
// V ring = 4 tiles (2 epoch-pairs); W = 2 pair-buffers (18.4 KB each).
// Barriers per epoch:
//   wfull[p] = id 1+p (256): producers arrive after BOTH chunks' W written;
//                            consumers sync before 8-ks MMA run.
//   wfree[p] = id 3+p (288): consumers arrive after MMA; producers + TMA sync
//                            (releases W pair AND V pair transitively).
// vfull[p] mbarrier: TMA completion of both tiles of pair p (producers wait).
// DEADLOCK FIX vs r15: producers sync wfree[p] BEFORE waiting vfull[p] —
// otherwise producers block on the TMA refill that the TMA warp can only
// issue after this same barrier completes.
// ---------------------------------------------------------------------------
#define SM_V   0                      // 4 x 10240 = 40960
#define SM_W   40960                  // 2 x 18432 = 36864
#define SM_Z   77824                  // 64 floats = 256B
#define SM_MB  78080                  // vfull[2]
#define SM_TOT 78112

__global__ __launch_bounds__(288, 2) void k_main(float* __restrict__ out) {
    extern __shared__ char smem[];
    const uint32_t sb = smem_u32(smem);
    const int h = blockIdx.y, i0 = blockIdx.x * 64;
    const int t = threadIdx.x, wid = t >> 5, lane = t & 31;
    const uint32_t vfull = sb + SM_MB;        // 2 x 8B
    float* zs = (float*)(smem + SM_Z);

    if (t == 0) {
        MBAR_INIT(vfull + 0, 1);
        MBAR_INIT(vfull + 8, 1);
    }
    if (t < 64) zs[t] = 0.f;
    __syncthreads();

    if (wid == 8) {
        // ----------------------------- TMA warp -----------------------------
        #pragma unroll 1
        for (int e = 0; e < 32; e++) {
            const int p = e & 1;
            if (e >= 2) BAR_SYNC(3 + p, 288);           // V pair fully released
            if (lane == 0) {
                asm volatile("mbarrier.arrive.expect_tx.shared.b64 _, [%0], %1;"
                             :: "r"(vfull + p * 8), "r"((uint32_t)(2 * VCH)) : "memory");
                #pragma unroll
                for (int c = 0; c < 2; c++) {
                    const char* src = g_Vt + (size_t)(h * 64 + 2 * e + c) * VCH;
                    uint64_t sg; asm("cvta.to.global.u64 %0, %1;" : "=l"(sg) : "l"(src));
                    asm volatile("cp.async.bulk.shared::cluster.global.mbarrier::complete_tx::bytes "
                                 "[%0], [%1], %2, [%3];"
                                 :: "r"(sb + SM_V + (p * 2 + c) * VCH), "l"(sg),
                                    "r"((uint32_t)VCH), "r"(vfull + p * 8) : "memory");
                }
            }
        }
    } else if (wid >= 4) {
        // ------------------------- 4 producer warps -------------------------
        const int q = wid - 4;                // j-quarter
        const int r0 = lane, r1 = lane + 32;
        const float4 id0 = g_idat[h][i0 + r0];
        const float4 id1 = g_idat[h][i0 + r1];
        const float th0 = -id0.x, A10 = id0.y, A20 = id0.z;
        const float th1 = -id1.x, A11 = id1.y, A21 = id1.z;
        float z0 = 0.f, z1 = 0.f;

        // stage A: 16-j strip of fp16 W for rows r0, r1 of chunk tile at vslot
        auto stageA = [&](int vslot, uint32_t woff, unsigned w0, unsigned w1) {
            const char* jb = smem + SM_V + vslot * VCH + 9216 + q * 64;
            uint32_t vv0[8], vv1[8];
            #pragma unroll
            for (int u = 0; u < 4; u++) {
                float4 f0 = *(const float4*)(jb + u * 16);          // dst
                float4 f1 = *(const float4*)(jb + 256 + u * 16);    // e1
                float4 f2 = *(const float4*)(jb + 512 + u * 16);    // e2
                float a0 = (f0.x >= th0) ? A10 * f1.x : A20 * f2.x;
                float a1 = (f0.y >= th0) ? A10 * f1.y : A20 * f2.y;
                float a2 = (f0.z >= th0) ? A10 * f1.z : A20 * f2.z;
                float a3 = (f0.w >= th0) ? A10 * f1.w : A20 * f2.w;
                a0 = ((w0 >> (4 * u + 0)) & 1u) ? a0 : 0.f;
                a1 = ((w0 >> (4 * u + 1)) & 1u) ? a1 : 0.f;
                a2 = ((w0 >> (4 * u + 2)) & 1u) ? a2 : 0.f;
                a3 = ((w0 >> (4 * u + 3)) & 1u) ? a3 : 0.f;
                z0 += (a0 + a1) + (a2 + a3);
                __half2 p0 = __floats2half2_rn(a0, a1);
                __half2 p1 = __floats2half2_rn(a2, a3);
                vv0[2 * u] = *(uint32_t*)&p0; vv0[2 * u + 1] = *(uint32_t*)&p1;
                float b0 = (f0.x >= th1) ? A11 * f1.x : A21 * f2.x;
                float b1 = (f0.y >= th1) ? A11 * f1.y : A21 * f2.y;
                float b2 = (f0.z >= th1) ? A11 * f1.z : A21 * f2.z;
                float b3 = (f0.w >= th1) ? A11 * f1.w : A21 * f2.w;
                b0 = ((w1 >> (4 * u + 0)) & 1u) ? b0 : 0.f;
                b1 = ((w1 >> (4 * u + 1)) & 1u) ? b1 : 0.f;
                b2 = ((w1 >> (4 * u + 2)) & 1u) ? b2 : 0.f;
                b3 = ((w1 >> (4 * u + 3)) & 1u) ? b3 : 0.f;
                z1 += (b0 + b1) + (b2 + b3);
                __half2 p2 = __floats2half2_rn(b0, b1);
                __half2 p3 = __floats2half2_rn(b2, b3);
                vv1[2 * u] = *(uint32_t*)&p2; vv1[2 * u + 1] = *(uint32_t*)&p3;
            }
            char* pr0 = smem + woff + r0 * 144 + q * 32;
            char* pr1 = smem + woff + r1 * 144 + q * 32;
            *(uint4*)(pr0)      = make_uint4(vv0[0], vv0[1], vv0[2], vv0[3]);
            *(uint4*)(pr0 + 16) = make_uint4(vv0[4], vv0[5], vv0[6], vv0[7]);
            *(uint4*)(pr1)      = make_uint4(vv1[0], vv1[1], vv1[2], vv1[3]);
            *(uint4*)(pr1 + 16) = make_uint4(vv1[4], vv1[5], vv1[6], vv1[7]);
        };

        #pragma unroll 1
        for (int e = 0; e < 32; e++) {
            const int p = e & 1;
            const int m0 = 2 * e, m1 = 2 * e + 1;
            // adjacency words for both chunks (in flight during waits)
            unsigned wa0 = g_adjT[m0 * 2 + (q >> 1)][i0 + r0] >> ((q & 1) * 16);
            unsigned wa1 = g_adjT[m0 * 2 + (q >> 1)][i0 + r1] >> ((q & 1) * 16);
            unsigned wb0 = g_adjT[m1 * 2 + (q >> 1)][i0 + r0] >> ((q & 1) * 16);
            unsigned wb1 = g_adjT[m1 * 2 + (q >> 1)][i0 + r1] >> ((q & 1) * 16);

            if (e >= 2) BAR_SYNC(3 + p, 288);           // W+V pair free (FIRST)
            MBAR_WAIT(vfull + p * 8, (e >> 1) & 1);     // then both V tiles

            stageA(p * 2,     SM_W + p * 18432,        wa0, wa1);
            stageA(p * 2 + 1, SM_W + p * 18432 + 9216, wb0, wb1);

            BAR_ARRIVE(1 + p, 256);                     // W pair full
        }
        atomicAdd(&zs[r0], z0);
        atomicAdd(&zs[r1], z1);
    } else {
        // ------------- 4 consumer warps (LDSM software-pipelined) -----------
        const int mgw = wid >> 1, ngw = wid & 1;
        const uint32_t aOff = (uint32_t)((mgw * 32 + (lane & 15)) * 144 + (lane >> 4) * 16);
        const uint32_t bO = (uint32_t)((lane & 15) * 144 + (lane >> 4) * 16 + ngw * 64);
        float d[2][4][4] = {};

        #pragma unroll 1
        for (int e = 0; e < 32; e++) {
            const int p = e & 1;
            BAR_SYNC(1 + p, 256);               // W pair + V pair ready
            #pragma unroll
            for (int c = 0; c < 2; c++) {
                const uint32_t vb = sb + SM_V + (uint32_t)(p * 2 + c) * VCH;
                const uint32_t aW = sb + SM_W + (uint32_t)(p * 18432 + c * 9216) + aOff;

                uint32_t af[2][2][4], bA[2][4], bB[2][4];
                LDSM_X4(af[0][0], aW);
                LDSM_X4(af[0][1], aW + 2304);
                LDSM_X4T(bA[0], vb + bO);
                LDSM_X4T(bB[0], vb + bO + 32);
                #pragma unroll
                for (int ks = 0; ks < 4; ks++) {
                    const int cur = ks & 1, nxt = cur ^ 1;
                    if (ks < 3) {
                        const uint32_t kb = vb + (uint32_t)(ks + 1) * 2304;
                        LDSM_X4(af[nxt][0], aW + (ks + 1) * 32);
                        LDSM_X4(af[nxt][1], aW + 2304 + (ks + 1) * 32);
                        LDSM_X4T(bA[nxt], kb + bO);
                        LDSM_X4T(bB[nxt], kb + bO + 32);
                    }
                    MMA(d[0][0], af[cur][0], bA[cur][0], bA[cur][1]);
                    MMA(d[0][1], af[cur][0], bA[cur][2], bA[cur][3]);
                    MMA(d[0][2], af[cur][0], bB[cur][0], bB[cur][1]);
                    MMA(d[0][3], af[cur][0], bB[cur][2], bB[cur][3]);
                    MMA(d[1][0], af[cur][1], bA[cur][0], bA[cur][1]);
                    MMA(d[1][1], af[cur][1], bA[cur][2], bA[cur][3]);
                    MMA(d[1][2], af[cur][1], bB[cur][0], bB[cur][1]);
                    MMA(d[1][3], af[cur][1], bB[cur][2], bB[cur][3]);
                }
            }
            BAR_ARRIVE(3 + p, 288);             // release W pair + V pair
        }

        __syncthreads();   // join with producers' zs atomics
        #pragma unroll
        for (int mt = 0; mt < 2; mt++) {
            int rlo = mgw * 32 + mt * 16 + (lane >> 2);
            int rhi = rlo + 8;
            float zlo = 1.0f / zs[rlo];
            float zhi = 1.0f / zs[rhi];
            #pragma unroll
            for (int nt = 0; nt < 4; nt++) {
                int col = h * OF + ngw * 32 + nt * 8 + (lane & 3) * 2;
                float* dd = d[mt][nt];
                float2 plo = make_float2(dd[0] * zlo, dd[1] * zlo);
                float2 phi = make_float2(dd[2] * zhi, dd[3] * zhi);
                *(float2*)(out + (size_t)(i0 + rlo) * (NH * OF) + col) = plo;
                *(float2*)(out + (size_t)(i0 + rhi) * (NH * OF) + col) = phi;
            }
        }
        return;
    }
    __syncthreads();   // producers + TMA warp join the epilogue barrier
}

// ---------------------------------------------------------------------------
extern "C" void kernel_launch(void* const* d_in, const int* in_sizes, int n_in,
                              void* d_out, int out_size) {
    const float* x   = (const float*)d_in[0];  // [4096, 256]
    const float* W   = (const float*)d_in[1];  // [4, 256, 64]
    const float* a   = (const float*)d_in[2];  // [4, 128]
    const int*   adj = (const int*)d_in[3];    // [4096, 4096]
    float* out = (float*)d_out;                // [4096, 256]
    (void)in_sizes; (void)n_in; (void)out_size;

    cudaFuncSetAttribute(k_main, cudaFuncAttributeMaxDynamicSharedMemorySize, SM_TOT);

    k_bitpack<<<(NN * NN / 16) / 256, 256>>>(adj);
    k_xtv<<<dim3(NN / 64, NH), 256>>>(x, W, a);
    k_main<<<dim3(NN / 64, NH), 288, SM_TOT>>>(out);
}